// round 15
// baseline (speedup 1.0000x reference)
#include <cuda_runtime.h>
#include <cuda_bf16.h>
#include <cstdint>

// ---------------- problem shape ----------------
#define B_    32
#define C_    64
#define HW_   4096
#define K_    512
#define NPIX  131072
#define NE    8388608
#define TPB   512
#define NWARP 16
#define TILE_M 256
#define NTILES (NPIX / TILE_M)   // 512
#define GRID_ 148
#define EPS_ACC 5e-5f            // acc-scale eps (dist eps = 2*EPS_ACC = 1e-4)
#define EW    36                 // permuted codebook row stride in u32 words
#define ZPAD  65                 // z tile row stride in f32

// ---------------- smem layout (bytes) ----------------
#define SM_E0    0               // 512 x 36 u32 = 73728
#define SM_E1    73728           // 73728
#define SM_Z     147456          // 256 x 65 f32 = 66560
#define SM_EN    214016          // 512 f32 (exact-path ||e||^2)
#define SM_INIT  216064          // 512 f32 (1 - en/2)
#define SM_M1    218112          // 256 f32
#define SM_K1    219136          // 256 i32
#define SM_M2    220160          // 256 f32
#define SM_K2    221184          // 256 i32
#define SM_M3    222208          // 256 f32
#define SM_KK    223232          // 256 i32
#define SM_FL    224256          // 256 i32
#define SM_FC    225280          // 8
#define SM_RED   225288          // 256 f32
#define SM_TOTAL 226312

__device__ float g_partials[GRID_];
__device__ unsigned int g_count;

typedef unsigned long long u64;

// ---------------- helpers ----------------
__device__ __forceinline__ void mma16816(float* c, const uint32_t* a,
                                         uint32_t b0, uint32_t b1) {
    asm volatile(
        "mma.sync.aligned.m16n8k16.row.col.f32.bf16.bf16.f32 "
        "{%0,%1,%2,%3}, {%4,%5,%6,%7}, {%8,%9}, {%0,%1,%2,%3};"
        : "+f"(c[0]), "+f"(c[1]), "+f"(c[2]), "+f"(c[3])
        : "r"(a[0]), "r"(a[1]), "r"(a[2]), "r"(a[3]), "r"(b0), "r"(b1));
}

__device__ __forceinline__ void bfsplit2(float x, float y,
                                         uint32_t& mn, uint32_t& rs) {
    __nv_bfloat16 hx = __float2bfloat16(x);
    __nv_bfloat16 hy = __float2bfloat16(y);
    float rx = x - __bfloat162float(hx);
    float ry = y - __bfloat162float(hy);
    __nv_bfloat162 m; m.x = hx; m.y = hy;
    __nv_bfloat162 r; r.x = __float2bfloat16(rx); r.y = __float2bfloat16(ry);
    mn = *(uint32_t*)&m;
    rs = *(uint32_t*)&r;
}

// branchless top-3 insert on acc scale (bigger = better); ~8 SASS ops.
// Tie order irrelevant: screen ties always land in the exact paths.
#define INS3F(a, kidx, m1, k1, m2, k2, m3)                      \
    do {                                                        \
        float _a = (a);                                         \
        bool _p1 = _a > (m1);                                   \
        bool _p2 = _a > (m2);                                   \
        (m3) = fminf((m2), fmaxf(_a, (m3)));                    \
        (m2) = fminf((m1), fmaxf(_a, (m2)));                    \
        (k2) = _p1 ? (k1) : (_p2 ? (kidx) : (k2));              \
        (m1) = fmaxf(_a, (m1));                                 \
        (k1) = _p1 ? (kidx) : (k1);                             \
    } while (0)

// packed f32x2 (exact-path arithmetic, identical to rounds 1..14)
__device__ __forceinline__ u64 fma2(u64 a, u64 b, u64 c) {
    u64 d;
    asm("fma.rn.f32x2 %0, %1, %2, %3;" : "=l"(d) : "l"(a), "l"(b), "l"(c));
    return d;
}
__device__ __forceinline__ u64 add2(u64 a, u64 b) {
    u64 d;
    asm("add.rn.f32x2 %0, %1, %2;" : "=l"(d) : "l"(a), "l"(b));
    return d;
}
__device__ __forceinline__ u64 pack2(float x, float y) {
    u64 u;
    asm("mov.b64 %0, {%1, %2};" : "=l"(u) : "f"(x), "f"(y));
    return u;
}
__device__ __forceinline__ float2 unpack2(u64 u) {
    float2 f;
    asm("mov.b64 {%0, %1}, %2;" : "=f"(f.x), "=f"(f.y) : "l"(u));
    return f;
}

// exact dist for one code, bit-identical to round-1 chain (zs = 64 f32 in smem)
__device__ __forceinline__ float exact_dist_k(const float* zs, const float* cb,
                                              int k, float zn, const float* en_s) {
    const ulonglong2* cp = (const ulonglong2*)(cb + (size_t)k * C_);
    u64 a0 = 0ull, a1 = 0ull, a2 = 0ull, a3 = 0ull;
    #pragma unroll
    for (int j = 0; j < 16; j += 2) {
        ulonglong2 v0 = cp[j];
        ulonglong2 v1 = cp[j + 1];
        a0 = fma2(pack2(zs[4 * j + 0], zs[4 * j + 1]), v0.x, a0);
        a1 = fma2(pack2(zs[4 * j + 2], zs[4 * j + 3]), v0.y, a1);
        a2 = fma2(pack2(zs[4 * j + 4], zs[4 * j + 5]), v1.x, a2);
        a3 = fma2(pack2(zs[4 * j + 6], zs[4 * j + 7]), v1.y, a3);
    }
    a0 = add2(a0, a1); a2 = add2(a2, a3); a0 = add2(a0, a2);
    float2 f = unpack2(a0);
    return (zn + en_s[k]) - 2.0f * (f.x + f.y);
}

// ---------------- kernel ----------------
__global__ void __launch_bounds__(TPB, 1)
vq_mma(const float* __restrict__ z, const float* __restrict__ cb,
       float* __restrict__ zq_out, float* __restrict__ idx_out,
       float* __restrict__ loss_out) {
    extern __shared__ char smem[];
    uint32_t* e0p = (uint32_t*)(smem + SM_E0);
    uint32_t* e1p = (uint32_t*)(smem + SM_E1);
    float* zsm   = (float*)(smem + SM_Z);
    float* en_s  = (float*)(smem + SM_EN);
    float* inits = (float*)(smem + SM_INIT);
    float* sm1   = (float*)(smem + SM_M1);
    int*   sk1   = (int*)  (smem + SM_K1);
    float* sm2   = (float*)(smem + SM_M2);
    int*   sk2   = (int*)  (smem + SM_K2);
    float* sm3   = (float*)(smem + SM_M3);
    int*   skk   = (int*)  (smem + SM_KK);
    int*   flst  = (int*)  (smem + SM_FL);
    int*   fcnt  = (int*)  (smem + SM_FC);
    float* red   = (float*)(smem + SM_RED);

    const int tid  = threadIdx.x;
    const int wid  = tid >> 5;
    const int lane = tid & 31;
    const int q    = lane & 3;
    const int g    = lane >> 2;

    // --- stage codebook ONCE: bf16 2-splits, fragment-permuted layout ---
    {
        const float2* cb2 = (const float2*)cb;
        for (int i = tid; i < K_ * 32; i += TPB) {
            const int n = i >> 5, w = i & 31;
            float2 v = cb2[i];
            uint32_t mn, rs;
            bfsplit2(v.x, v.y, mn, rs);
            const int rem = w & 7;
            const int nw = (rem & 3) * 8 + (w >> 3) * 2 + (rem >> 2);
            e0p[n * EW + nw] = mn;
            e1p[n * EW + nw] = rs;
        }
    }
    for (int k = tid; k < K_; k += TPB) {
        const float* cp = cb + k * C_;
        float s = 0.f;
        #pragma unroll
        for (int c = 0; c < C_; ++c) s = fmaf(cp[c], cp[c], s);
        en_s[k]  = s;
        inits[k] = 1.0f - 0.5f * s;   // acc init: acc_final = 1 - en/2 + dot
    }

    float lsum = 0.f;

    // --- persistent tile loop ---
    for (int tile = blockIdx.x; tile < NTILES; tile += GRID_) {
        __syncthreads();
        if (tid == 0) *fcnt = 0;

        const int bb  = tile >> 4;
        const int hwb = (tile & 15) * TILE_M;
        const float* zb = z + (size_t)bb * (C_ * HW_);

        // stage z tile (256 pixels, transposed to [pixel][channel])
        for (int i = tid; i < 64 * 64; i += TPB) {
            const int c = i >> 6, j = i & 63;
            float4 v = *(const float4*)(zb + c * HW_ + hwb + j * 4);
            zsm[(j * 4 + 0) * ZPAD + c] = v.x;
            zsm[(j * 4 + 1) * ZPAD + c] = v.y;
            zsm[(j * 4 + 2) * ZPAD + c] = v.z;
            zsm[(j * 4 + 3) * ZPAD + c] = v.w;
        }
        __syncthreads();

        // build A fragments: rows wid*16 + {g, g+8}
        uint32_t az0[4][4], az1[4][4];
        {
            const int r0 = wid * 16 + g;
            const int r1 = r0 + 8;
            #pragma unroll
            for (int ks = 0; ks < 4; ++ks) {
                const int kc = ks * 16 + 2 * q;
                bfsplit2(zsm[r0 * ZPAD + kc],     zsm[r0 * ZPAD + kc + 1], az0[ks][0], az1[ks][0]);
                bfsplit2(zsm[r1 * ZPAD + kc],     zsm[r1 * ZPAD + kc + 1], az0[ks][1], az1[ks][1]);
                bfsplit2(zsm[r0 * ZPAD + kc + 8], zsm[r0 * ZPAD + kc + 9], az0[ks][2], az1[ks][2]);
                bfsplit2(zsm[r1 * ZPAD + kc + 8], zsm[r1 * ZPAD + kc + 9], az0[ks][3], az1[ks][3]);
            }
        }

        // screen trackers: (m1,k1,m2,k2,m3) per tracker; a -> row wid*16+g, b -> +8
        float m1a = -3.4e38f, m2a = -3.4e38f, m3a = -3.4e38f;
        float m1b = -3.4e38f, m2b = -3.4e38f, m3b = -3.4e38f;
        int   k1a = 0, k2a = 0, k1b = 0, k2b = 0;

        // strength-reduced fragment pointers (advance 8*EW words per nt)
        const uint4* p0 = (const uint4*)(e0p + g * EW + q * 8);
        const uint4* p1 = (const uint4*)(e1p + g * EW + q * 8);
        const float2* ivp = (const float2*)(inits + 2 * q);

        #pragma unroll 1
        for (int nt = 0; nt < 64; ++nt) {
            uint4 b0a = p0[0], b0b = p0[1];
            uint4 b1a = p1[0], b1b = p1[1];
            p0 += (8 * EW) / 4;
            p1 += (8 * EW) / 4;

            const int kc = nt * 8 + 2 * q;
            float2 iv = ivp[nt * 4];
            float accA[4] = {iv.x, iv.y, iv.x, iv.y};   // z0*e0 + z1*e0 (8 MMAs)
            float accB[4] = {0.f, 0.f, 0.f, 0.f};       // z0*e1 (4 MMAs)

            mma16816(accA, az0[0], b0a.x, b0a.y);
            mma16816(accB, az0[0], b1a.x, b1a.y);
            mma16816(accA, az0[1], b0a.z, b0a.w);
            mma16816(accB, az0[1], b1a.z, b1a.w);
            mma16816(accA, az0[2], b0b.x, b0b.y);
            mma16816(accB, az0[2], b1b.x, b1b.y);
            mma16816(accA, az0[3], b0b.z, b0b.w);
            mma16816(accB, az0[3], b1b.z, b1b.w);
            mma16816(accA, az1[0], b0a.x, b0a.y);
            mma16816(accA, az1[1], b0a.z, b0a.w);
            mma16816(accA, az1[2], b0b.x, b0b.y);
            mma16816(accA, az1[3], b0b.z, b0b.w);

            float s0 = accA[0] + accB[0];
            float s1 = accA[1] + accB[1];
            float s2 = accA[2] + accB[2];
            float s3 = accA[3] + accB[3];

            INS3F(s0, kc,     m1a, k1a, m2a, k2a, m3a);
            INS3F(s1, kc + 1, m1a, k1a, m2a, k2a, m3a);
            INS3F(s2, kc,     m1b, k1b, m2b, k2b, m3b);
            INS3F(s3, kc + 1, m1b, k1b, m2b, k2b, m3b);
        }

        // reduce top-3 across the 4 q-lanes of each row (desc merge)
        #pragma unroll
        for (int t = 0; t < 2; ++t) {
            float m1 = t ? m1b : m1a, m2 = t ? m2b : m2a, m3 = t ? m3b : m3a;
            int   k1 = t ? k1b : k1a, k2 = t ? k2b : k2a;
            #pragma unroll
            for (int off = 1; off <= 2; off <<= 1) {
                float om1 = __shfl_xor_sync(0xFFFFFFFFu, m1, off);
                float om2 = __shfl_xor_sync(0xFFFFFFFFu, m2, off);
                float om3 = __shfl_xor_sync(0xFFFFFFFFu, m3, off);
                int   ok1 = __shfl_xor_sync(0xFFFFFFFFu, k1, off);
                int   ok2 = __shfl_xor_sync(0xFFFFFFFFu, k2, off);
                float n1, n2, n3; int nk1, nk2;
                if (m1 >= om1) {
                    n1 = m1; nk1 = k1;
                    if (m2 >= om1) { n2 = m2;  nk2 = k2;  n3 = fmaxf(m3, om1); }
                    else           { n2 = om1; nk2 = ok1; n3 = fmaxf(m2, om2); }
                } else {
                    n1 = om1; nk1 = ok1;
                    if (om2 >= m1) { n2 = om2; nk2 = ok2; n3 = fmaxf(om3, m1); }
                    else           { n2 = m1;  nk2 = k1;  n3 = fmaxf(om2, m2); }
                }
                m1 = n1; m2 = n2; m3 = n3; k1 = nk1; k2 = nk2;
            }
            if (q == 0) {
                const int row = wid * 16 + t * 8 + g;
                sm1[row] = m1; sk1[row] = k1;
                sm2[row] = m2; sk2[row] = k2;
                sm3[row] = m3;
            }
        }
        __syncthreads();

        // decision pass: first 256 threads resolve kk
        if (tid < TILE_M) {
            const int m = tid;
            const float a1 = sm1[m], a2 = sm2[m], a3 = sm3[m];
            const int k1 = sk1[m], k2 = sk2[m];
            int kk;
            if (a1 - a2 >= EPS_ACC) {
                kk = k1;
            } else if (a1 - a3 >= EPS_ACC) {
                // exact 2-candidate compare (round-1 arithmetic)
                const float* zs = zsm + m * ZPAD;
                float zn = 0.f;
                #pragma unroll
                for (int i = 0; i < 32; ++i) {
                    float x = zs[2 * i], y = zs[2 * i + 1];
                    zn = fmaf(x, x, zn); zn = fmaf(y, y, zn);
                }
                float dA = exact_dist_k(zs, cb, k1, zn, en_s);
                float dB = exact_dist_k(zs, cb, k2, zn, en_s);
                kk = (dB < dA || (dB == dA && k2 < k1)) ? k2 : k1;
            } else {
                kk = -1;
                flst[atomicAdd(fcnt, 1)] = m;
            }
            skk[m] = kk;
            if (kk >= 0) idx_out[tile * TILE_M + m] = (float)kk;
        }
        __syncthreads();

        // writeback pass: all 512 threads, 2 per pixel
        {
            const int m  = tid & 255;
            const int hf = tid >> 8;          // channel half
            const int kk = skk[m];
            if (kk >= 0) {
                const float* zs = zsm + m * ZPAD + hf * 32;
                const float4* cr = (const float4*)(cb + kk * C_) + hf * 8;
                float* zo = zq_out + (size_t)bb * (C_ * HW_) + (size_t)(hf * 32) * HW_ + hwb + m;
                float ls = 0.f;
                #pragma unroll
                for (int j4 = 0; j4 < 8; ++j4) {
                    float4 qv = cr[j4];
                    const float qa[4] = {qv.x, qv.y, qv.z, qv.w};
                    #pragma unroll
                    for (int t = 0; t < 4; ++t) {
                        const int c = j4 * 4 + t;
                        float x = zs[c];
                        float d = qa[t] - x;
                        ls = fmaf(d, d, ls);
                        zo[c * HW_] = x + d;
                    }
                }
                lsum += ls;
            }
        }
        __syncthreads();

        // rare full exact fallback: one warp per flagged pixel (round-1 arithmetic)
        const int F = *fcnt;
        for (int e = wid; e < F; e += NWARP) {
            const int mm = flst[e];
            const float* zs = zsm + mm * ZPAD;
            float zn = 0.f;
            #pragma unroll
            for (int i = 0; i < 32; ++i) {
                float x = zs[2 * i], y = zs[2 * i + 1];
                zn = fmaf(x, x, zn); zn = fmaf(y, y, zn);
            }
            float best = 3.402823466e38f;
            int   bk   = 0;
            #pragma unroll 1
            for (int t = 0; t < 16; ++t) {
                const int k = lane + (t << 5);
                float dist = exact_dist_k(zs, cb, k, zn, en_s);
                if (dist < best) { best = dist; bk = k; }
            }
            #pragma unroll
            for (int off = 16; off > 0; off >>= 1) {
                float ob = __shfl_down_sync(0xFFFFFFFFu, best, off);
                int   ok = __shfl_down_sync(0xFFFFFFFFu, bk, off);
                if (ob < best || (ob == best && ok < bk)) { best = ob; bk = ok; }
            }
            if (lane == 0) {
                const int p  = tile * TILE_M + mm;
                const int hw = hwb + mm;
                const float* cbv = cb + bk * C_;
                float* zo = zq_out + (size_t)bb * (C_ * HW_) + hw;
                float ls = 0.f;
                #pragma unroll
                for (int c = 0; c < C_; ++c) {
                    float x = zs[c];
                    float d = cbv[c] - x;
                    ls = fmaf(d, d, ls);
                    zo[c * HW_] = x + d;
                }
                lsum += ls;
                idx_out[p] = (float)bk;
            }
        }
    }

    // --- loss reduction ---
    __syncthreads();
    #pragma unroll
    for (int off = 16; off > 0; off >>= 1)
        lsum += __shfl_down_sync(0xFFFFFFFFu, lsum, off);
    if (lane == 0) red[wid] = lsum;
    __syncthreads();
    if (tid == 0) {
        float t = 0.f;
        #pragma unroll
        for (int w = 0; w < NWARP; ++w) t += red[w];
        g_partials[blockIdx.x] = t;
        __threadfence();
        unsigned int old = atomicAdd(&g_count, 1u);
        *fcnt = (old == GRID_ - 1) ? 1 : 0;
    }
    __syncthreads();
    if (*fcnt) {
        if (tid < 256) {
            float v = 0.f;
            if (tid < GRID_)
                asm volatile("ld.global.cg.f32 %0, [%1];" : "=f"(v) : "l"(g_partials + tid));
            red[tid] = v;
        }
        __syncthreads();
        for (int off = 128; off > 0; off >>= 1) {
            if (tid < off) red[tid] += red[tid + off];
            __syncthreads();
        }
        if (tid == 0) {
            float qv = red[0] / (float)NE;   // q_loss == e_loss numerically
            loss_out[0] = qv + 0.25f * qv;
            g_count = 0;                     // reset for next graph replay
        }
    }
}

extern "C" void kernel_launch(void* const* d_in, const int* in_sizes, int n_in,
                              void* d_out, int out_size) {
    const float* z  = (const float*)d_in[0];   // z_e [32,64,64,64] f32
    const float* cb = (const float*)d_in[1];   // codebook [512,64] f32
    float* out  = (float*)d_out;
    float* zq   = out;               // [NE]
    float* idx  = out + NE;          // [NPIX]
    float* loss = out + NE + NPIX;   // [1]

    cudaFuncSetAttribute(vq_mma, cudaFuncAttributeMaxDynamicSharedMemorySize, SM_TOTAL);
    vq_mma<<<GRID_, TPB, SM_TOTAL>>>(z, cb, zq, idx, loss);
}

// round 16
// speedup vs baseline: 1.1127x; 1.1127x over previous
#include <cuda_runtime.h>
#include <cuda_bf16.h>
#include <cstdint>

// ---------------- problem shape ----------------
#define B_    32
#define C_    64
#define HW_   4096
#define K_    512
#define NPIX  131072
#define NE    8388608
#define TPB   512
#define NWARP 16
#define GRID_ 148
#define P1TILES 444              // 3 * 148 tiles of 256 px (balanced)
#define P2UNITS 136              // 68 tiles of 256 px -> 136 half-tiles of 128 px
#define P2BASE  113664           // 444 * 256
#define EPS_ACC 5e-5f            // acc-scale eps (dist eps = 2*EPS_ACC = 1e-4)
#define EW    36                 // permuted codebook row stride in u32 words
#define ZPAD  65                 // z tile row stride in f32

// ---------------- smem layout (bytes) ----------------
#define SM_E0    0               // 512 x 36 u32 = 73728
#define SM_E1    73728           // 73728
#define SM_Z     147456          // 256 x 65 f32 = 66560
#define SM_EN    214016          // 512 f32
#define SM_INIT  216064          // 512 f32 (1 - en/2)
#define SM_M1    218112          // 256 f32
#define SM_K1    219136          // 256 i32
#define SM_M2    220160          // 256 f32
#define SM_K2    221184          // 256 i32
#define SM_M3    222208          // 256 f32
#define SM_KK    223232          // 256 i32
#define SM_FL    224256          // 256 i32
#define SM_FC    225280          // 8
#define SM_RED   225288          // 256 f32
#define SM_TOTAL 226312

__device__ float g_partials[GRID_];
__device__ unsigned int g_count;

typedef unsigned long long u64;

// ---------------- helpers ----------------
__device__ __forceinline__ void mma16816(float* c, const uint32_t* a,
                                         uint32_t b0, uint32_t b1) {
    asm volatile(
        "mma.sync.aligned.m16n8k16.row.col.f32.bf16.bf16.f32 "
        "{%0,%1,%2,%3}, {%4,%5,%6,%7}, {%8,%9}, {%0,%1,%2,%3};"
        : "+f"(c[0]), "+f"(c[1]), "+f"(c[2]), "+f"(c[3])
        : "r"(a[0]), "r"(a[1]), "r"(a[2]), "r"(a[3]), "r"(b0), "r"(b1));
}

__device__ __forceinline__ void bfsplit2(float x, float y,
                                         uint32_t& mn, uint32_t& rs) {
    __nv_bfloat16 hx = __float2bfloat16(x);
    __nv_bfloat16 hy = __float2bfloat16(y);
    float rx = x - __bfloat162float(hx);
    float ry = y - __bfloat162float(hy);
    __nv_bfloat162 m; m.x = hx; m.y = hy;
    __nv_bfloat162 r; r.x = __float2bfloat16(rx); r.y = __float2bfloat16(ry);
    mn = *(uint32_t*)&m;
    rs = *(uint32_t*)&r;
}

// branchless top-3 insert on acc scale (bigger = better).
// Tie order irrelevant: screen ties always land in the exact paths.
#define INS3F(a, kidx, m1, k1, m2, k2, m3)                      \
    do {                                                        \
        float _a = (a);                                         \
        bool _p1 = _a > (m1);                                   \
        bool _p2 = _a > (m2);                                   \
        (m3) = fminf((m2), fmaxf(_a, (m3)));                    \
        (m2) = fminf((m1), fmaxf(_a, (m2)));                    \
        (k2) = _p1 ? (k1) : (_p2 ? (kidx) : (k2));              \
        (m1) = fmaxf(_a, (m1));                                 \
        (k1) = _p1 ? (kidx) : (k1);                             \
    } while (0)

// desc merge of two top-3 lists (values desc, ties -> exact path anyway)
#define MERGE3(m1, k1, m2, k2, m3, om1, ok1, om2, ok2, om3)     \
    do {                                                        \
        float n1, n2, n3; int nk1, nk2;                         \
        if ((m1) >= (om1)) {                                    \
            n1 = (m1); nk1 = (k1);                              \
            if ((m2) >= (om1)) { n2 = (m2);  nk2 = (k2);  n3 = fmaxf((m3), (om1)); } \
            else               { n2 = (om1); nk2 = (ok1); n3 = fmaxf((m2), (om2)); } \
        } else {                                                \
            n1 = (om1); nk1 = (ok1);                            \
            if ((om2) >= (m1)) { n2 = (om2); nk2 = (ok2); n3 = fmaxf((om3), (m1)); } \
            else               { n2 = (m1);  nk2 = (k1);  n3 = fmaxf((om2), (m2)); } \
        }                                                       \
        (m1) = n1; (m2) = n2; (m3) = n3; (k1) = nk1; (k2) = nk2; \
    } while (0)

// packed f32x2 (exact-path arithmetic, identical to rounds 1..15)
__device__ __forceinline__ u64 fma2(u64 a, u64 b, u64 c) {
    u64 d;
    asm("fma.rn.f32x2 %0, %1, %2, %3;" : "=l"(d) : "l"(a), "l"(b), "l"(c));
    return d;
}
__device__ __forceinline__ u64 add2(u64 a, u64 b) {
    u64 d;
    asm("add.rn.f32x2 %0, %1, %2;" : "=l"(d) : "l"(a), "l"(b));
    return d;
}
__device__ __forceinline__ u64 pack2(float x, float y) {
    u64 u;
    asm("mov.b64 %0, {%1, %2};" : "=l"(u) : "f"(x), "f"(y));
    return u;
}
__device__ __forceinline__ float2 unpack2(u64 u) {
    float2 f;
    asm("mov.b64 {%0, %1}, %2;" : "=f"(f.x), "=f"(f.y) : "l"(u));
    return f;
}

// exact dist for one code, bit-identical to round-1 chain (zs = 64 f32 in smem)
__device__ __forceinline__ float exact_dist_k(const float* zs, const float* cb,
                                              int k, float zn, const float* en_s) {
    const ulonglong2* cp = (const ulonglong2*)(cb + (size_t)k * C_);
    u64 a0 = 0ull, a1 = 0ull, a2 = 0ull, a3 = 0ull;
    #pragma unroll
    for (int j = 0; j < 16; j += 2) {
        ulonglong2 v0 = cp[j];
        ulonglong2 v1 = cp[j + 1];
        a0 = fma2(pack2(zs[4 * j + 0], zs[4 * j + 1]), v0.x, a0);
        a1 = fma2(pack2(zs[4 * j + 2], zs[4 * j + 3]), v0.y, a1);
        a2 = fma2(pack2(zs[4 * j + 4], zs[4 * j + 5]), v1.x, a2);
        a3 = fma2(pack2(zs[4 * j + 6], zs[4 * j + 7]), v1.y, a3);
    }
    a0 = add2(a0, a1); a2 = add2(a2, a3); a0 = add2(a0, a2);
    float2 f = unpack2(a0);
    return (zn + en_s[k]) - 2.0f * (f.x + f.y);
}

// ---------------- kernel ----------------
__global__ void __launch_bounds__(TPB, 1)
vq_mma(const float* __restrict__ z, const float* __restrict__ cb,
       float* __restrict__ zq_out, float* __restrict__ idx_out,
       float* __restrict__ loss_out) {
    extern __shared__ char smem[];
    uint32_t* e0p = (uint32_t*)(smem + SM_E0);
    uint32_t* e1p = (uint32_t*)(smem + SM_E1);
    float* zsm   = (float*)(smem + SM_Z);
    float* en_s  = (float*)(smem + SM_EN);
    float* inits = (float*)(smem + SM_INIT);
    float* sm1   = (float*)(smem + SM_M1);
    int*   sk1   = (int*)  (smem + SM_K1);
    float* sm2   = (float*)(smem + SM_M2);
    int*   sk2   = (int*)  (smem + SM_K2);
    float* sm3   = (float*)(smem + SM_M3);
    int*   skk   = (int*)  (smem + SM_KK);
    int*   flst  = (int*)  (smem + SM_FL);
    int*   fcnt  = (int*)  (smem + SM_FC);
    float* red   = (float*)(smem + SM_RED);

    const int tid  = threadIdx.x;
    const int wid  = tid >> 5;
    const int lane = tid & 31;
    const int q    = lane & 3;
    const int g    = lane >> 2;

    // --- stage codebook ONCE: bf16 2-splits, fragment-permuted layout ---
    {
        const float2* cb2 = (const float2*)cb;
        for (int i = tid; i < K_ * 32; i += TPB) {
            const int n = i >> 5, w = i & 31;
            float2 v = cb2[i];
            uint32_t mn, rs;
            bfsplit2(v.x, v.y, mn, rs);
            const int rem = w & 7;
            const int nw = (rem & 3) * 8 + (w >> 3) * 2 + (rem >> 2);
            e0p[n * EW + nw] = mn;
            e1p[n * EW + nw] = rs;
        }
    }
    for (int k = tid; k < K_; k += TPB) {
        const float* cp = cb + k * C_;
        float s = 0.f;
        #pragma unroll
        for (int c = 0; c < C_; ++c) s = fmaf(cp[c], cp[c], s);
        en_s[k]  = s;
        inits[k] = 1.0f - 0.5f * s;   // acc init: acc_final = 1 - en/2 + dot
    }

    float lsum = 0.f;

    // --- job loop: jobs 0..2 = balanced 256-px tiles; job 3 = 128-px half-tile ---
    for (int job = 0; job < 4; ++job) {
        int pbase, pixcnt, rfi, ntb, ntn;
        if (job < 3) {
            pbase  = (blockIdx.x + job * GRID_) * 256;   // tiles 0..443
            pixcnt = 256; rfi = wid; ntb = 0; ntn = 64;
        } else {
            if (blockIdx.x >= P2UNITS) break;            // 12 CTAs done
            pbase  = P2BASE + blockIdx.x * 128;          // tiles 444..511, halved
            pixcnt = 128; rfi = wid & 7; ntb = (wid >> 3) * 32; ntn = 32;
        }
        const int bb  = pbase >> 12;
        const int hwb = pbase & 4095;
        const float* zb = z + (size_t)bb * (C_ * HW_);

        __syncthreads();
        if (tid == 0) *fcnt = 0;

        // stage z tile (pixcnt pixels, transposed to [pixel][channel])
        {
            const int jsh = (job < 3) ? 6 : 5;           // float4 groups per channel
            const int jmask = (1 << jsh) - 1;
            for (int i = tid; i < (64 << jsh); i += TPB) {
                const int c = i >> jsh, j = i & jmask;
                float4 v = *(const float4*)(zb + c * HW_ + hwb + j * 4);
                zsm[(j * 4 + 0) * ZPAD + c] = v.x;
                zsm[(j * 4 + 1) * ZPAD + c] = v.y;
                zsm[(j * 4 + 2) * ZPAD + c] = v.z;
                zsm[(j * 4 + 3) * ZPAD + c] = v.w;
            }
        }
        __syncthreads();

        // build A fragments: rows rfi*16 + {g, g+8}
        uint32_t az0[4][4], az1[4][4];
        {
            const int r0 = rfi * 16 + g;
            const int r1 = r0 + 8;
            #pragma unroll
            for (int ks = 0; ks < 4; ++ks) {
                const int kc = ks * 16 + 2 * q;
                bfsplit2(zsm[r0 * ZPAD + kc],     zsm[r0 * ZPAD + kc + 1], az0[ks][0], az1[ks][0]);
                bfsplit2(zsm[r1 * ZPAD + kc],     zsm[r1 * ZPAD + kc + 1], az0[ks][1], az1[ks][1]);
                bfsplit2(zsm[r0 * ZPAD + kc + 8], zsm[r0 * ZPAD + kc + 9], az0[ks][2], az1[ks][2]);
                bfsplit2(zsm[r1 * ZPAD + kc + 8], zsm[r1 * ZPAD + kc + 9], az0[ks][3], az1[ks][3]);
            }
        }

        // screen trackers (m1,k1,m2,k2,m3); a -> row rfi*16+g, b -> +8
        float m1a = -3.4e38f, m2a = -3.4e38f, m3a = -3.4e38f;
        float m1b = -3.4e38f, m2b = -3.4e38f, m3b = -3.4e38f;
        int   k1a = 0, k2a = 0, k1b = 0, k2b = 0;

        const uint4* p0 = (const uint4*)(e0p + (ntb * 8 + g) * EW + q * 8);
        const uint4* p1 = (const uint4*)(e1p + (ntb * 8 + g) * EW + q * 8);

        #pragma unroll 1
        for (int it = 0; it < ntn; ++it) {
            uint4 b0a = p0[0], b0b = p0[1];
            uint4 b1a = p1[0], b1b = p1[1];
            p0 += (8 * EW) / 4;
            p1 += (8 * EW) / 4;

            const int kc = (ntb + it) * 8 + 2 * q;
            float2 iv = *(const float2*)(inits + kc);
            float accA[4] = {iv.x, iv.y, iv.x, iv.y};   // z0*e0 + z1*e0
            float accB[4] = {0.f, 0.f, 0.f, 0.f};       // z0*e1

            mma16816(accA, az0[0], b0a.x, b0a.y);
            mma16816(accB, az0[0], b1a.x, b1a.y);
            mma16816(accA, az0[1], b0a.z, b0a.w);
            mma16816(accB, az0[1], b1a.z, b1a.w);
            mma16816(accA, az0[2], b0b.x, b0b.y);
            mma16816(accB, az0[2], b1b.x, b1b.y);
            mma16816(accA, az0[3], b0b.z, b0b.w);
            mma16816(accB, az0[3], b1b.z, b1b.w);
            mma16816(accA, az1[0], b0a.x, b0a.y);
            mma16816(accA, az1[1], b0a.z, b0a.w);
            mma16816(accA, az1[2], b0b.x, b0b.y);
            mma16816(accA, az1[3], b0b.z, b0b.w);

            float s0 = accA[0] + accB[0];
            float s1 = accA[1] + accB[1];
            float s2 = accA[2] + accB[2];
            float s3 = accA[3] + accB[3];

            INS3F(s0, kc,     m1a, k1a, m2a, k2a, m3a);
            INS3F(s1, kc + 1, m1a, k1a, m2a, k2a, m3a);
            INS3F(s2, kc,     m1b, k1b, m2b, k2b, m3b);
            INS3F(s3, kc + 1, m1b, k1b, m2b, k2b, m3b);
        }

        // reduce top-3 across the 4 q-lanes of each row
        #pragma unroll
        for (int t = 0; t < 2; ++t) {
            float m1 = t ? m1b : m1a, m2 = t ? m2b : m2a, m3 = t ? m3b : m3a;
            int   k1 = t ? k1b : k1a, k2 = t ? k2b : k2a;
            #pragma unroll
            for (int off = 1; off <= 2; off <<= 1) {
                float om1 = __shfl_xor_sync(0xFFFFFFFFu, m1, off);
                float om2 = __shfl_xor_sync(0xFFFFFFFFu, m2, off);
                float om3 = __shfl_xor_sync(0xFFFFFFFFu, m3, off);
                int   ok1 = __shfl_xor_sync(0xFFFFFFFFu, k1, off);
                int   ok2 = __shfl_xor_sync(0xFFFFFFFFu, k2, off);
                MERGE3(m1, k1, m2, k2, m3, om1, ok1, om2, ok2, om3);
            }
            if (q == 0) {
                // phase 2: code-half 1 writes to slots 128..255
                const int slot = rfi * 16 + t * 8 + g + ((job < 3) ? 0 : (wid >> 3) * 128);
                sm1[slot] = m1; sk1[slot] = k1;
                sm2[slot] = m2; sk2[slot] = k2;
                sm3[slot] = m3;
            }
        }
        __syncthreads();

        // phase 2 only: merge the two code-half tracker sets per row
        if (job == 3) {
            if (tid < 128) {
                float m1 = sm1[tid], m2 = sm2[tid], m3 = sm3[tid];
                int   k1 = sk1[tid], k2 = sk2[tid];
                float om1 = sm1[tid + 128], om2 = sm2[tid + 128], om3 = sm3[tid + 128];
                int   ok1 = sk1[tid + 128], ok2 = sk2[tid + 128];
                MERGE3(m1, k1, m2, k2, m3, om1, ok1, om2, ok2, om3);
                sm1[tid] = m1; sk1[tid] = k1;
                sm2[tid] = m2; sk2[tid] = k2;
                sm3[tid] = m3;
            }
            __syncthreads();
        }

        // decision pass: one thread per pixel
        if (tid < pixcnt) {
            const int m = tid;
            const float a1 = sm1[m], a2 = sm2[m], a3 = sm3[m];
            const int k1 = sk1[m], k2 = sk2[m];
            int kk;
            if (a1 - a2 >= EPS_ACC) {
                kk = k1;
            } else if (a1 - a3 >= EPS_ACC) {
                // exact 2-candidate compare (round-1 arithmetic)
                const float* zs = zsm + m * ZPAD;
                float zn = 0.f;
                #pragma unroll
                for (int i = 0; i < 32; ++i) {
                    float x = zs[2 * i], y = zs[2 * i + 1];
                    zn = fmaf(x, x, zn); zn = fmaf(y, y, zn);
                }
                float dA = exact_dist_k(zs, cb, k1, zn, en_s);
                float dB = exact_dist_k(zs, cb, k2, zn, en_s);
                kk = (dB < dA || (dB == dA && k2 < k1)) ? k2 : k1;
            } else {
                kk = -1;
                flst[atomicAdd(fcnt, 1)] = m;
            }
            skk[m] = kk;
            if (kk >= 0) idx_out[pbase + m] = (float)kk;
        }
        __syncthreads();

        // writeback pass: all 512 threads share the pixels
        {
            const int psh   = (job < 3) ? 8 : 7;
            const int m     = tid & ((1 << psh) - 1);
            const int hf    = tid >> psh;              // channel chunk index
            const int chunk = 64 >> (((job < 3) ? 9 : 9) - psh);  // 32 or 16
            const int j4max = chunk >> 2;
            const int kk = skk[m];
            if (kk >= 0) {
                const float* zs = zsm + m * ZPAD + hf * chunk;
                const float4* cr = (const float4*)(cb + kk * C_) + hf * j4max;
                float* zo = zq_out + (size_t)bb * (C_ * HW_) + (size_t)(hf * chunk) * HW_ + hwb + m;
                float ls = 0.f;
                for (int j4 = 0; j4 < j4max; ++j4) {
                    float4 qv = cr[j4];
                    const float qa[4] = {qv.x, qv.y, qv.z, qv.w};
                    #pragma unroll
                    for (int t = 0; t < 4; ++t) {
                        const int c = j4 * 4 + t;
                        float x = zs[c];
                        float d = qa[t] - x;
                        ls = fmaf(d, d, ls);
                        zo[c * HW_] = x + d;
                    }
                }
                lsum += ls;
            }
        }
        __syncthreads();

        // rare full exact fallback: one warp per flagged pixel (round-1 arithmetic)
        const int F = *fcnt;
        for (int e = wid; e < F; e += NWARP) {
            const int mm = flst[e];
            const float* zs = zsm + mm * ZPAD;
            float zn = 0.f;
            #pragma unroll
            for (int i = 0; i < 32; ++i) {
                float x = zs[2 * i], y = zs[2 * i + 1];
                zn = fmaf(x, x, zn); zn = fmaf(y, y, zn);
            }
            float best = 3.402823466e38f;
            int   bk   = 0;
            #pragma unroll 1
            for (int t = 0; t < 16; ++t) {
                const int k = lane + (t << 5);
                float dist = exact_dist_k(zs, cb, k, zn, en_s);
                if (dist < best) { best = dist; bk = k; }
            }
            #pragma unroll
            for (int off = 16; off > 0; off >>= 1) {
                float ob = __shfl_down_sync(0xFFFFFFFFu, best, off);
                int   ok = __shfl_down_sync(0xFFFFFFFFu, bk, off);
                if (ob < best || (ob == best && ok < bk)) { best = ob; bk = ok; }
            }
            if (lane == 0) {
                const float* cbv = cb + bk * C_;
                float* zo = zq_out + (size_t)bb * (C_ * HW_) + hwb + mm;
                float ls = 0.f;
                #pragma unroll
                for (int c = 0; c < C_; ++c) {
                    float x = zs[c];
                    float d = cbv[c] - x;
                    ls = fmaf(d, d, ls);
                    zo[c * HW_] = x + d;
                }
                lsum += ls;
                idx_out[pbase + mm] = (float)bk;
            }
        }
    }

    // --- loss reduction ---
    __syncthreads();
    #pragma unroll
    for (int off = 16; off > 0; off >>= 1)
        lsum += __shfl_down_sync(0xFFFFFFFFu, lsum, off);
    if (lane == 0) red[wid] = lsum;
    __syncthreads();
    if (tid == 0) {
        float t = 0.f;
        #pragma unroll
        for (int w = 0; w < NWARP; ++w) t += red[w];
        g_partials[blockIdx.x] = t;
        __threadfence();
        unsigned int old = atomicAdd(&g_count, 1u);
        *fcnt = (old == GRID_ - 1) ? 1 : 0;
    }
    __syncthreads();
    if (*fcnt) {
        if (tid < 256) {
            float v = 0.f;
            if (tid < GRID_)
                asm volatile("ld.global.cg.f32 %0, [%1];" : "=f"(v) : "l"(g_partials + tid));
            red[tid] = v;
        }
        __syncthreads();
        for (int off = 128; off > 0; off >>= 1) {
            if (tid < off) red[tid] += red[tid + off];
            __syncthreads();
        }
        if (tid == 0) {
            float qv = red[0] / (float)NE;   // q_loss == e_loss numerically
            loss_out[0] = qv + 0.25f * qv;
            g_count = 0;                     // reset for next graph replay
        }
    }
}

extern "C" void kernel_launch(void* const* d_in, const int* in_sizes, int n_in,
                              void* d_out, int out_size) {
    const float* z  = (const float*)d_in[0];   // z_e [32,64,64,64] f32
    const float* cb = (const float*)d_in[1];   // codebook [512,64] f32
    float* out  = (float*)d_out;
    float* zq   = out;               // [NE]
    float* idx  = out + NE;          // [NPIX]
    float* loss = out + NE + NPIX;   // [1]

    cudaFuncSetAttribute(vq_mma, cudaFuncAttributeMaxDynamicSharedMemorySize, SM_TOTAL);
    vq_mma<<<GRID_, TPB, SM_TOTAL>>>(z, cb, zq, idx, loss);
}